// round 1
// baseline (speedup 1.0000x reference)
#include <cuda_runtime.h>
#include <math.h>

#define NN 20000
#define EE 320000
#define DD 128
#define HH 3
#define HD (HH*DD)      /* 384 */
#define LL 3
#define GG 64
#define TWO_D (2*DD)    /* 256 */
#define NEG_SLOPE 0.2f

// ---------------- scratch (device globals; no allocation allowed) ----------------
__device__ float g_h[(size_t)NN*HD];
__device__ float g_agg[(size_t)NN*HD];
__device__ float g_featA[(size_t)NN*DD];
__device__ float g_featB[(size_t)NN*DD];
__device__ float g_hidden[(size_t)NN*TWO_D];
__device__ float g_gate[NN];
__device__ float g_sns[NN*HH];
__device__ float g_snd[NN*HH];
__device__ int   g_deg[NN];
__device__ int   g_rowptr[NN+1];
__device__ int   g_cursor[NN];
__device__ int   g_csrsrc[EE];
__device__ int   g_gstart[GG];
__device__ int   g_gend[GG];

// ---------------- small utility kernels ----------------
__global__ void zero_f_kernel(float* p, int n) {
    int i = blockIdx.x*blockDim.x + threadIdx.x;
    if (i < n) p[i] = 0.f;
}

__global__ void copy_f_kernel(float* dstp, const float* srcp, int n) {
    int i = blockIdx.x*blockDim.x + threadIdx.x;
    if (i < n) dstp[i] = srcp[i];
}

__global__ void csr_init_kernel() {
    int i = blockIdx.x*blockDim.x + threadIdx.x;
    if (i < NN) g_deg[i] = 0;
}

__global__ void hist_kernel(const int* __restrict__ dst) {
    int e = blockIdx.x*blockDim.x + threadIdx.x;
    if (e < EE) atomicAdd(&g_deg[dst[e]], 1);
}

__global__ void scan_kernel() {
    __shared__ int part[1024];
    int t = threadIdx.x;
    const int CH = 20;                      // 1024*20 >= 20000
    int base = t * CH;
    int local[CH];
    int s = 0;
#pragma unroll
    for (int i = 0; i < CH; i++) {
        int idx = base + i;
        int v = (idx < NN) ? g_deg[idx] : 0;
        local[i] = s;
        s += v;
    }
    part[t] = s;
    __syncthreads();
    for (int off = 1; off < 1024; off <<= 1) {
        int v = (t >= off) ? part[t - off] : 0;
        __syncthreads();
        part[t] += v;
        __syncthreads();
    }
    int offset = (t > 0) ? part[t - 1] : 0;
#pragma unroll
    for (int i = 0; i < CH; i++) {
        int idx = base + i;
        if (idx < NN) {
            int r = offset + local[i];
            g_rowptr[idx] = r;
            g_cursor[idx] = r;
        }
    }
    if (t == 0) g_rowptr[NN] = part[1023];
}

__global__ void scatter_kernel(const int* __restrict__ src, const int* __restrict__ dst) {
    int e = blockIdx.x*blockDim.x + threadIdx.x;
    if (e < EE) {
        int p = atomicAdd(&g_cursor[dst[e]], 1);
        g_csrsrc[p] = src[e];
    }
}

__global__ void gb_init_kernel() {
    int g = threadIdx.x;
    if (g < GG) { g_gstart[g] = NN; g_gend[g] = 0; }
}

__global__ void gbounds_kernel(const int* __restrict__ gid) {
    int i = blockIdx.x*blockDim.x + threadIdx.x;
    if (i < NN) {
        int g = gid[i];
        atomicMin(&g_gstart[g], i);
        atomicMax(&g_gend[g], i + 1);
    }
}

// ---------------- SGEMM: C[M,Nd] = A[M,K] @ B[Nd,K]^T (+bias)(relu)(+resid) ----------------
// 128x128 tile, BK=8, 256 threads, 8x8 per-thread microtile.
__global__ void __launch_bounds__(256, 2) sgemm_nt(
    int M, int Nd, int K,
    const float* __restrict__ A, const float* __restrict__ B,
    const float* __restrict__ bias, const float* __restrict__ resid,
    float* __restrict__ C, int do_relu)
{
    __shared__ float As[8][128];
    __shared__ float Bs[8][128];
    const int tid = threadIdx.x;
    const int m0 = blockIdx.x * 128;
    const int n0 = blockIdx.y * 128;
    const int tx = tid & 15;
    const int ty = tid >> 4;
    const int lrow = tid >> 1;          // 0..127
    const int lk   = (tid & 1) * 4;     // 0 or 4

    float acc[8][8];
#pragma unroll
    for (int i = 0; i < 8; i++)
#pragma unroll
        for (int j = 0; j < 8; j++) acc[i][j] = 0.f;

    const bool arow_ok = (m0 + lrow) < M;
    const float* Aptr = A + (size_t)(m0 + lrow) * K + lk;
    const float* Bptr = B + (size_t)(n0 + lrow) * K + lk;

    for (int k0 = 0; k0 < K; k0 += 8) {
        float4 av = arow_ok ? *(const float4*)(Aptr + k0) : make_float4(0.f, 0.f, 0.f, 0.f);
        float4 bv = *(const float4*)(Bptr + k0);
        As[lk + 0][lrow] = av.x; As[lk + 1][lrow] = av.y;
        As[lk + 2][lrow] = av.z; As[lk + 3][lrow] = av.w;
        Bs[lk + 0][lrow] = bv.x; Bs[lk + 1][lrow] = bv.y;
        Bs[lk + 2][lrow] = bv.z; Bs[lk + 3][lrow] = bv.w;
        __syncthreads();
#pragma unroll
        for (int k = 0; k < 8; k++) {
            float4 a0 = *(const float4*)&As[k][ty * 8];
            float4 a1 = *(const float4*)&As[k][ty * 8 + 4];
            float4 b0 = *(const float4*)&Bs[k][tx * 8];
            float4 b1 = *(const float4*)&Bs[k][tx * 8 + 4];
            float ra[8] = {a0.x, a0.y, a0.z, a0.w, a1.x, a1.y, a1.z, a1.w};
            float rb[8] = {b0.x, b0.y, b0.z, b0.w, b1.x, b1.y, b1.z, b1.w};
#pragma unroll
            for (int i = 0; i < 8; i++)
#pragma unroll
                for (int j = 0; j < 8; j++)
                    acc[i][j] += ra[i] * rb[j];
        }
        __syncthreads();
    }

#pragma unroll
    for (int i = 0; i < 8; i++) {
        int m = m0 + ty * 8 + i;
        if (m >= M) break;
        float* crow = C + (size_t)m * Nd;
        const float* rrow = resid ? (resid + (size_t)m * Nd) : nullptr;
#pragma unroll
        for (int j = 0; j < 8; j++) {
            int n = n0 + tx * 8 + j;
            float v = acc[i][j];
            if (bias) v += bias[n];
            if (do_relu) v = fmaxf(v, 0.f);
            if (rrow) v += rrow[n];
            crow[n] = v;
        }
    }
}

// ---------------- per-node attention scores: s_ns/s_nd = <h[n,h,:], a_*[h,:]> ----------------
__global__ void attn_score_kernel(const float* __restrict__ ans, const float* __restrict__ andv) {
    int w = (blockIdx.x * blockDim.x + threadIdx.x) >> 5;
    int lane = threadIdx.x & 31;
    if (w >= NN) return;
    float s0 = 0.f, s1 = 0.f, s2 = 0.f, t0 = 0.f, t1 = 0.f, t2 = 0.f;
    const float* hr = g_h + (size_t)w * HD;
#pragma unroll
    for (int j = 0; j < 12; j++) {
        int f = j * 32 + lane;
        float hv = hr[f];
        float av = ans[f];
        float bv = andv[f];
        if (j < 4)      { s0 += hv * av; t0 += hv * bv; }
        else if (j < 8) { s1 += hv * av; t1 += hv * bv; }
        else            { s2 += hv * av; t2 += hv * bv; }
    }
#pragma unroll
    for (int o = 16; o; o >>= 1) {
        s0 += __shfl_xor_sync(0xffffffffu, s0, o);
        s1 += __shfl_xor_sync(0xffffffffu, s1, o);
        s2 += __shfl_xor_sync(0xffffffffu, s2, o);
        t0 += __shfl_xor_sync(0xffffffffu, t0, o);
        t1 += __shfl_xor_sync(0xffffffffu, t1, o);
        t2 += __shfl_xor_sync(0xffffffffu, t2, o);
    }
    if (lane == 0) {
        g_sns[w * 3 + 0] = s0; g_sns[w * 3 + 1] = s1; g_sns[w * 3 + 2] = s2;
        g_snd[w * 3 + 0] = t0; g_snd[w * 3 + 1] = t1; g_snd[w * 3 + 2] = t2;
    }
}

// ---------------- edge softmax + aggregation: one warp per dst node ----------------
__device__ __forceinline__ float leaky(float x) { return x > 0.f ? x : NEG_SLOPE * x; }

__global__ void gat_edge_kernel() {
    int v = (blockIdx.x * blockDim.x + threadIdx.x) >> 5;
    int lane = threadIdx.x & 31;
    if (v >= NN) return;
    int beg = g_rowptr[v], end = g_rowptr[v + 1];
    float snd0 = g_snd[v * 3 + 0], snd1 = g_snd[v * 3 + 1], snd2 = g_snd[v * 3 + 2];

    // pass 1: segment max per head
    float m0 = -1e30f, m1 = -1e30f, m2 = -1e30f;
    for (int e = beg + lane; e < end; e += 32) {
        int s = g_csrsrc[e];
        m0 = fmaxf(m0, leaky(g_sns[s * 3 + 0] + snd0));
        m1 = fmaxf(m1, leaky(g_sns[s * 3 + 1] + snd1));
        m2 = fmaxf(m2, leaky(g_sns[s * 3 + 2] + snd2));
    }
#pragma unroll
    for (int o = 16; o; o >>= 1) {
        m0 = fmaxf(m0, __shfl_xor_sync(0xffffffffu, m0, o));
        m1 = fmaxf(m1, __shfl_xor_sync(0xffffffffu, m1, o));
        m2 = fmaxf(m2, __shfl_xor_sync(0xffffffffu, m2, o));
    }

    // pass 2: exp, sum, weighted gather-accumulate (whole warp per edge)
    float acc[12];
#pragma unroll
    for (int j = 0; j < 12; j++) acc[j] = 0.f;
    float ws0 = 0.f, ws1 = 0.f, ws2 = 0.f;

    for (int e = beg; e < end; e++) {
        int s = g_csrsrc[e];                                 // uniform across warp
        float w0 = __expf(leaky(g_sns[s * 3 + 0] + snd0) - m0);
        float w1 = __expf(leaky(g_sns[s * 3 + 1] + snd1) - m1);
        float w2 = __expf(leaky(g_sns[s * 3 + 2] + snd2) - m2);
        ws0 += w0; ws1 += w1; ws2 += w2;
        const float* hr = g_h + (size_t)s * HD;
#pragma unroll
        for (int j = 0; j < 12; j++) {
            float wv = (j < 4) ? w0 : (j < 8) ? w1 : w2;
            acc[j] += wv * hr[j * 32 + lane];
        }
    }

    float r0 = ws0 > 0.f ? 1.f / ws0 : 0.f;
    float r1 = ws1 > 0.f ? 1.f / ws1 : 0.f;
    float r2 = ws2 > 0.f ? 1.f / ws2 : 0.f;
    float* ar = g_agg + (size_t)v * HD;
#pragma unroll
    for (int j = 0; j < 12; j++) {
        float rv = (j < 4) ? r0 : (j < 8) ? r1 : r2;
        ar[j * 32 + lane] = acc[j] * rv;
    }
}

// ---------------- gate: g = <hidden[n,:], p2_w> + p2_b ----------------
__global__ void gate_kernel(const float* __restrict__ p2w, const float* __restrict__ p2b) {
    int w = (blockIdx.x * blockDim.x + threadIdx.x) >> 5;
    int lane = threadIdx.x & 31;
    if (w >= NN) return;
    const float* hr = g_hidden + (size_t)w * TWO_D;
    float s = 0.f;
#pragma unroll
    for (int j = 0; j < 8; j++) {
        int f = j * 32 + lane;
        s += hr[f] * p2w[f];
    }
#pragma unroll
    for (int o = 16; o; o >>= 1) s += __shfl_xor_sync(0xffffffffu, s, o);
    if (lane == 0) g_gate[w] = s + p2b[0];
}

// ---------------- global attention pooling: one block (128 thr) per graph ----------------
__global__ void pool_kernel(const float* __restrict__ feat, float* __restrict__ out, float scale) {
    int g = blockIdx.x;
    int d = threadIdx.x;   // 0..127 — owns output dim d
    int s = g_gstart[g], e = g_gend[g];
    __shared__ float red[128];

    // max
    float m = -1e30f;
    for (int i = s + d; i < e; i += 128) m = fmaxf(m, g_gate[i]);
    red[d] = m; __syncthreads();
    for (int o = 64; o; o >>= 1) { if (d < o) red[d] = fmaxf(red[d], red[d + o]); __syncthreads(); }
    m = red[0]; __syncthreads();

    // sum exp
    float sum = 0.f;
    for (int i = s + d; i < e; i += 128) sum += __expf(g_gate[i] - m);
    red[d] = sum; __syncthreads();
    for (int o = 64; o; o >>= 1) { if (d < o) red[d] += red[d + o]; __syncthreads(); }
    sum = red[0]; __syncthreads();

    // weighted accumulate along dim d
    float accv = 0.f;
    for (int i = s; i < e; i++) {
        float wv = __expf(g_gate[i] - m);
        accv += wv * feat[(size_t)i * DD + d];
    }
    if (e > s && sum > 0.f) out[g * DD + d] += scale * accv / sum;
}

// ---------------- launch ----------------
extern "C" void kernel_launch(void* const* d_in, const int* in_sizes, int n_in,
                              void* d_out, int out_size)
{
    const float* feat    = (const float*)d_in[0];
    const int*   src     = (const int*)d_in[1];
    const int*   dst     = (const int*)d_in[2];
    const int*   gid     = (const int*)d_in[3];
    const float* fc_w    = (const float*)d_in[4];
    const float* a_ns    = (const float*)d_in[5];
    const float* a_nd    = (const float*)d_in[6];
    const float* trans_w = (const float*)d_in[7];
    const float* trans_b = (const float*)d_in[8];
    const float* p1_w    = (const float*)d_in[9];
    const float* p1_b    = (const float*)d_in[10];
    const float* p2_w    = (const float*)d_in[11];
    const float* p2_b    = (const float*)d_in[12];
    float* out = (float*)d_out;

    float *p_h, *p_agg, *p_featA, *p_featB, *p_hidden;
    cudaGetSymbolAddress((void**)&p_h, g_h);
    cudaGetSymbolAddress((void**)&p_agg, g_agg);
    cudaGetSymbolAddress((void**)&p_featA, g_featA);
    cudaGetSymbolAddress((void**)&p_featB, g_featB);
    cudaGetSymbolAddress((void**)&p_hidden, g_hidden);

    // init output + input copy
    zero_f_kernel<<<(GG * DD + 255) / 256, 256>>>(out, GG * DD);
    copy_f_kernel<<<(NN * DD + 255) / 256, 256>>>(p_featA, feat, NN * DD);

    // CSR build (by dst)
    csr_init_kernel<<<(NN + 255) / 256, 256>>>();
    hist_kernel<<<(EE + 255) / 256, 256>>>(dst);
    scan_kernel<<<1, 1024>>>();
    scatter_kernel<<<(EE + 255) / 256, 256>>>(src, dst);

    // graph node ranges (node_gid is sorted)
    gb_init_kernel<<<1, GG>>>();
    gbounds_kernel<<<(NN + 255) / 256, 256>>>(gid);

    const int warpBlocks = (NN + 7) / 8;   // 8 warps / 256-thread block
    for (int d = 0; d < LL; d++) {
        float* fin  = (d % 2 == 0) ? p_featA : p_featB;
        float* fout = (d % 2 == 0) ? p_featB : p_featA;

        // h = feat_in @ fc_w[d]^T        [N,384]
        dim3 g1((NN + 127) / 128, HD / 128);
        sgemm_nt<<<g1, 256>>>(NN, HD, DD, fin, fc_w + (size_t)d * HD * DD,
                              nullptr, nullptr, p_h, 0);

        // per-node attention scores
        attn_score_kernel<<<warpBlocks, 256>>>(a_ns + (size_t)d * HD, a_nd + (size_t)d * HD);

        // edge softmax + aggregate -> agg [N,384]
        gat_edge_kernel<<<warpBlocks, 256>>>();

        // feat_out = relu?(agg @ trans_w[d]^T + trans_b[d]) + feat_in
        dim3 g2((NN + 127) / 128, DD / 128);
        sgemm_nt<<<g2, 256>>>(NN, DD, HD, p_agg, trans_w + (size_t)d * DD * HD,
                              trans_b + (size_t)d * DD, fin, fout, (d < LL - 1) ? 1 : 0);

        // pooling gate MLP layer 1: hidden = relu(feat_out @ p1_w[d]^T + p1_b[d])  [N,256]
        dim3 g3((NN + 127) / 128, TWO_D / 128);
        sgemm_nt<<<g3, 256>>>(NN, TWO_D, DD, fout, p1_w + (size_t)d * TWO_D * DD,
                              p1_b + (size_t)d * TWO_D, nullptr, p_hidden, 1);

        // gate = hidden @ p2_w[d]^T + p2_b[d]
        gate_kernel<<<warpBlocks, 256>>>(p2_w + (size_t)d * TWO_D, p2_b + d);

        // per-graph softmax-pool, accumulate mean over layers
        pool_kernel<<<GG, 128>>>(fout, out, 1.0f / LL);
    }
}

// round 4
// speedup vs baseline: 1.8385x; 1.8385x over previous
#include <cuda_runtime.h>
#include <cuda_bf16.h>
#include <stdint.h>
#include <math.h>

typedef unsigned int u32;

#define NN 20000
#define EE 320000
#define DD 128
#define HH 3
#define HD (HH*DD)      /* 384 */
#define LL 3
#define GG 64
#define TWO_D (2*DD)    /* 256 */
#define NEG_SLOPE 0.2f

// ---------------- scratch (device globals; no allocation allowed) ----------------
__device__ float g_h[(size_t)NN*HD];
__device__ float g_featA[(size_t)NN*DD];
__device__ float g_featB[(size_t)NN*DD];
__device__ float g_hidden[(size_t)NN*TWO_D];
__device__ float g_gate[NN];
__device__ float g_sns[NN*HH];
__device__ float g_snd[NN*HH];
__device__ int   g_deg[NN];
__device__ int   g_rowptr[NN+1];
__device__ int   g_cursor[NN];
__device__ int   g_csrsrc[EE];
__device__ int   g_gstart[GG];
__device__ int   g_gend[GG];

// bf16 split buffers
__device__ __nv_bfloat16 g_fhiA[(size_t)NN*DD];
__device__ __nv_bfloat16 g_floA[(size_t)NN*DD];
__device__ __nv_bfloat16 g_fhiB[(size_t)NN*DD];
__device__ __nv_bfloat16 g_floB[(size_t)NN*DD];
__device__ __nv_bfloat16 g_agghi[(size_t)NN*HD];
__device__ __nv_bfloat16 g_agglo[(size_t)NN*HD];
__device__ __nv_bfloat16 g_wfchi[(size_t)LL*HD*DD];
__device__ __nv_bfloat16 g_wfclo[(size_t)LL*HD*DD];
__device__ __nv_bfloat16 g_wtrhi[(size_t)LL*DD*HD];
__device__ __nv_bfloat16 g_wtrlo[(size_t)LL*DD*HD];
__device__ __nv_bfloat16 g_wp1hi[(size_t)LL*TWO_D*DD];
__device__ __nv_bfloat16 g_wp1lo[(size_t)LL*TWO_D*DD];

__device__ __forceinline__ void split_bf16(float v, __nv_bfloat16& hi, __nv_bfloat16& lo) {
    hi = __float2bfloat16_rn(v);
    lo = __float2bfloat16_rn(v - __bfloat162float(hi));
}

// ---------------- small utility kernels ----------------
__global__ void zero_f_kernel(float* p, int n) {
    int i = blockIdx.x*blockDim.x + threadIdx.x;
    if (i < n) p[i] = 0.f;
}

__global__ void copy_split_kernel(const float* __restrict__ srcp) {
    int i = blockIdx.x*blockDim.x + threadIdx.x;
    if (i < NN*DD) {
        float v = srcp[i];
        g_featA[i] = v;
        __nv_bfloat16 hi, lo; split_bf16(v, hi, lo);
        g_fhiA[i] = hi; g_floA[i] = lo;
    }
}

__global__ void convert_split_kernel(const float* __restrict__ srcp,
                                     __nv_bfloat16* __restrict__ hi,
                                     __nv_bfloat16* __restrict__ lo, int n) {
    int i = blockIdx.x*blockDim.x + threadIdx.x;
    if (i < n) {
        __nv_bfloat16 h, l; split_bf16(srcp[i], h, l);
        hi[i] = h; lo[i] = l;
    }
}

__global__ void csr_init_kernel() {
    int i = blockIdx.x*blockDim.x + threadIdx.x;
    if (i < NN) g_deg[i] = 0;
}

__global__ void hist_kernel(const int* __restrict__ dst) {
    int e = blockIdx.x*blockDim.x + threadIdx.x;
    if (e < EE) atomicAdd(&g_deg[dst[e]], 1);
}

__global__ void scan_kernel() {
    __shared__ int part[1024];
    int t = threadIdx.x;
    const int CH = 20;
    int base = t * CH;
    int local[CH];
    int s = 0;
#pragma unroll
    for (int i = 0; i < CH; i++) {
        int idx = base + i;
        int v = (idx < NN) ? g_deg[idx] : 0;
        local[i] = s;
        s += v;
    }
    part[t] = s;
    __syncthreads();
    for (int off = 1; off < 1024; off <<= 1) {
        int v = (t >= off) ? part[t - off] : 0;
        __syncthreads();
        part[t] += v;
        __syncthreads();
    }
    int offset = (t > 0) ? part[t - 1] : 0;
#pragma unroll
    for (int i = 0; i < CH; i++) {
        int idx = base + i;
        if (idx < NN) {
            int r = offset + local[i];
            g_rowptr[idx] = r;
            g_cursor[idx] = r;
        }
    }
    if (t == 0) g_rowptr[NN] = part[1023];
}

__global__ void scatter_kernel(const int* __restrict__ src, const int* __restrict__ dst) {
    int e = blockIdx.x*blockDim.x + threadIdx.x;
    if (e < EE) {
        int p = atomicAdd(&g_cursor[dst[e]], 1);
        g_csrsrc[p] = src[e];
    }
}

__global__ void gb_init_kernel() {
    int g = threadIdx.x;
    if (g < GG) { g_gstart[g] = NN; g_gend[g] = 0; }
}

__global__ void gbounds_kernel(const int* __restrict__ gid) {
    int i = blockIdx.x*blockDim.x + threadIdx.x;
    if (i < NN) {
        int g = gid[i];
        atomicMin(&g_gstart[g], i);
        atomicMax(&g_gend[g], i + 1);
    }
}

// ---------------- tensor-core GEMM: C[M,Nd] = A[M,K] @ B[Nd,K]^T ----------------
// bf16 split-precision: C = Ahi*Bhi + Ahi*Blo + Alo*Bhi (fp32 accumulate)
// Block tile 128(M) x 64(N), K-chunk 32, 256 threads (8 warps 4x2),
// warp tile 32x32 via mma.sync.m16n8k16 + ldmatrix, double-buffered smem.

__device__ __forceinline__ void ldm_x4(u32 addr, u32& r0, u32& r1, u32& r2, u32& r3) {
    asm volatile("ldmatrix.sync.aligned.m8n8.x4.shared.b16 {%0,%1,%2,%3}, [%4];"
        : "=r"(r0), "=r"(r1), "=r"(r2), "=r"(r3) : "r"(addr));
}

__device__ __forceinline__ void mma16816(float* c, const u32* a, const u32* b) {
    asm volatile(
        "mma.sync.aligned.m16n8k16.row.col.f32.bf16.bf16.f32 "
        "{%0,%1,%2,%3}, {%4,%5,%6,%7}, {%8,%9}, {%0,%1,%2,%3};"
        : "+f"(c[0]), "+f"(c[1]), "+f"(c[2]), "+f"(c[3])
        : "r"(a[0]), "r"(a[1]), "r"(a[2]), "r"(a[3]), "r"(b[0]), "r"(b[1]));
}

__device__ __forceinline__ uint4 ldz(const __nv_bfloat16* p, int row, int K, int kb, int M) {
    if (row < M) return *(const uint4*)(p + (size_t)row * K + kb);
    uint4 z; z.x = 0u; z.y = 0u; z.z = 0u; z.w = 0u;
    return z;
}

#define A_PAD 40   /* row stride in bf16 elems: 80B -> 20-bank shift, conflict-free */
#define SA_MAT (128*A_PAD)
#define SB_MAT (64*A_PAD)

#define GFETCH(kc) { \
    int kb = ((kc) << 5) + aq; \
    pa00 = ldz(Ahi, m0 + ar0,      K, kb, M); \
    pa01 = ldz(Ahi, m0 + ar0 + 64, K, kb, M); \
    pa10 = ldz(Alo, m0 + ar0,      K, kb, M); \
    pa11 = ldz(Alo, m0 + ar0 + 64, K, kb, M); \
    pb0  = *(const uint4*)(Bhi + (size_t)(n0 + br0) * K + kb); \
    pb1  = *(const uint4*)(Blo + (size_t)(n0 + br0) * K + kb); \
}

#define GSTORE(st) { \
    *(uint4*)(sA + ((st)*2+0)*SA_MAT + ar0*A_PAD + aq)        = pa00; \
    *(uint4*)(sA + ((st)*2+0)*SA_MAT + (ar0+64)*A_PAD + aq)   = pa01; \
    *(uint4*)(sA + ((st)*2+1)*SA_MAT + ar0*A_PAD + aq)        = pa10; \
    *(uint4*)(sA + ((st)*2+1)*SA_MAT + (ar0+64)*A_PAD + aq)   = pa11; \
    *(uint4*)(sB + ((st)*2+0)*SB_MAT + br0*A_PAD + aq)        = pb0; \
    *(uint4*)(sB + ((st)*2+1)*SB_MAT + br0*A_PAD + aq)        = pb1; \
}

__global__ void __launch_bounds__(256, 2) gemm_bf16split(
    int M, int Nd, int K,
    const __nv_bfloat16* __restrict__ Ahi, const __nv_bfloat16* __restrict__ Alo,
    const __nv_bfloat16* __restrict__ Bhi, const __nv_bfloat16* __restrict__ Blo,
    const float* __restrict__ bias, const float* __restrict__ resid,
    float* __restrict__ C, __nv_bfloat16* __restrict__ Chi, __nv_bfloat16* __restrict__ Clo,
    int do_relu)
{
    extern __shared__ __nv_bfloat16 smem[];
    __nv_bfloat16* sA = smem;                // [2 stages][2 hl][128*A_PAD]
    __nv_bfloat16* sB = smem + 2*2*SA_MAT;   // [2 stages][2 hl][64*A_PAD]

    const int tid  = threadIdx.x;
    const int lane = tid & 31;
    const int w    = tid >> 5;
    const int wm   = w & 3;     // 4 warps along M (32 rows each)
    const int wn   = w >> 2;    // 2 warps along N (32 cols each)
    const int m0   = blockIdx.x * 128;
    const int n0   = blockIdx.y * 64;
    const int nk   = K >> 5;

    float acc[2][4][4];
#pragma unroll
    for (int a = 0; a < 2; a++)
#pragma unroll
        for (int b = 0; b < 4; b++)
#pragma unroll
            for (int c = 0; c < 4; c++) acc[a][b][c] = 0.f;

    const u32 sA_u = (u32)__cvta_generic_to_shared(sA);
    const u32 sB_u = (u32)__cvta_generic_to_shared(sB);

    // ldmatrix lane addressing
    const int a_row_in = (lane & 7) + ((lane >> 3) & 1) * 8;
    const int a_kofs   = (lane >> 4) * 8;
    const int b_sub    = lane >> 3;
    const int b_row_in = (lane & 7) + (b_sub >> 1) * 8;
    const int b_kofs   = (b_sub & 1) * 8;

    // per-thread global load mapping (32 k-elems per row chunk, 4 threads/row)
    const int ar0 = tid >> 2;
    const int aq  = (tid & 3) * 8;
    const int br0 = tid >> 2;

    uint4 pa00, pa01, pa10, pa11, pb0, pb1;

    GFETCH(0);
    GSTORE(0);
    __syncthreads();

    for (int kc = 0; kc < nk; kc++) {
        const int cur = kc & 1;
        if (kc + 1 < nk) GFETCH(kc + 1);

#pragma unroll
        for (int ks = 0; ks < 2; ks++) {
            u32 Af[2][2][4];
            u32 Bf[2][4][2];
#pragma unroll
            for (int hl = 0; hl < 2; hl++) {
                const u32 abase = sA_u +
                    (u32)(((cur * 2 + hl) * 128 + wm * 32) * A_PAD) * 2u;
#pragma unroll
                for (int mt = 0; mt < 2; mt++) {
                    u32 addr = abase +
                        (u32)((mt * 16 + a_row_in) * A_PAD + ks * 16 + a_kofs) * 2u;
                    ldm_x4(addr, Af[hl][mt][0], Af[hl][mt][1], Af[hl][mt][2], Af[hl][mt][3]);
                }
                const u32 bbase = sB_u +
                    (u32)(((cur * 2 + hl) * 64 + wn * 32) * A_PAD) * 2u;
#pragma unroll
                for (int pr = 0; pr < 2; pr++) {
                    u32 addr2 = bbase +
                        (u32)((pr * 16 + b_row_in) * A_PAD + ks * 16 + b_kofs) * 2u;
                    u32 q0, q1, q2, q3;
                    ldm_x4(addr2, q0, q1, q2, q3);
                    Bf[hl][pr * 2 + 0][0] = q0; Bf[hl][pr * 2 + 0][1] = q1;
                    Bf[hl][pr * 2 + 1][0] = q2; Bf[hl][pr * 2 + 1][1] = q3;
                }
            }
#pragma unroll
            for (int mt = 0; mt < 2; mt++)
#pragma unroll
                for (int nt = 0; nt < 4; nt++) {
                    mma16816(acc[mt][nt], Af[0][mt], Bf[0][nt]);  // hi*hi
                    mma16816(acc[mt][nt], Af[0][mt], Bf[1][nt]);  // hi*lo
                    mma16816(acc[mt][nt], Af[1][mt], Bf[0][nt]);  // lo*hi
                }
        }

        if (kc + 1 < nk) GSTORE((kc + 1) & 1);
        __syncthreads();
    }

    // epilogue
    const int gr = lane >> 2;
    const int gc = (lane & 3) * 2;
#pragma unroll
    for (int mt = 0; mt < 2; mt++) {
#pragma unroll
        for (int half = 0; half < 2; half++) {
            int m = m0 + wm * 32 + mt * 16 + gr + half * 8;
            if (m >= M) continue;
#pragma unroll
            for (int nt = 0; nt < 4; nt++) {
                int n = n0 + wn * 32 + nt * 8 + gc;
                float v0 = acc[mt][nt][half * 2 + 0];
                float v1 = acc[mt][nt][half * 2 + 1];
                if (bias) { v0 += bias[n]; v1 += bias[n + 1]; }
                if (do_relu) { v0 = fmaxf(v0, 0.f); v1 = fmaxf(v1, 0.f); }
                if (resid) {
                    v0 += resid[(size_t)m * Nd + n];
                    v1 += resid[(size_t)m * Nd + n + 1];
                }
                float2 vv; vv.x = v0; vv.y = v1;
                *(float2*)(C + (size_t)m * Nd + n) = vv;
                if (Chi) {
                    __nv_bfloat16 h0, l0, h1, l1;
                    split_bf16(v0, h0, l0);
                    split_bf16(v1, h1, l1);
                    __nv_bfloat162 hh; hh.x = h0; hh.y = h1;
                    __nv_bfloat162 ll; ll.x = l0; ll.y = l1;
                    *(__nv_bfloat162*)(Chi + (size_t)m * Nd + n) = hh;
                    *(__nv_bfloat162*)(Clo + (size_t)m * Nd + n) = ll;
                }
            }
        }
    }
}

// ---------------- per-node attention scores ----------------
__global__ void attn_score_kernel(const float* __restrict__ ans, const float* __restrict__ andv) {
    int w = (blockIdx.x * blockDim.x + threadIdx.x) >> 5;
    int lane = threadIdx.x & 31;
    if (w >= NN) return;
    float s0 = 0.f, s1 = 0.f, s2 = 0.f, t0 = 0.f, t1 = 0.f, t2 = 0.f;
    const float* hr = g_h + (size_t)w * HD;
#pragma unroll
    for (int j = 0; j < 12; j++) {
        int f = j * 32 + lane;
        float hv = hr[f];
        float av = ans[f];
        float bv = andv[f];
        if (j < 4)      { s0 += hv * av; t0 += hv * bv; }
        else if (j < 8) { s1 += hv * av; t1 += hv * bv; }
        else            { s2 += hv * av; t2 += hv * bv; }
    }
#pragma unroll
    for (int o = 16; o; o >>= 1) {
        s0 += __shfl_xor_sync(0xffffffffu, s0, o);
        s1 += __shfl_xor_sync(0xffffffffu, s1, o);
        s2 += __shfl_xor_sync(0xffffffffu, s2, o);
        t0 += __shfl_xor_sync(0xffffffffu, t0, o);
        t1 += __shfl_xor_sync(0xffffffffu, t1, o);
        t2 += __shfl_xor_sync(0xffffffffu, t2, o);
    }
    if (lane == 0) {
        g_sns[w * 3 + 0] = s0; g_sns[w * 3 + 1] = s1; g_sns[w * 3 + 2] = s2;
        g_snd[w * 3 + 0] = t0; g_snd[w * 3 + 1] = t1; g_snd[w * 3 + 2] = t2;
    }
}

// ---------------- edge softmax + aggregation: one warp per dst node ----------------
__device__ __forceinline__ float leaky(float x) { return x > 0.f ? x : NEG_SLOPE * x; }

__global__ void gat_edge_kernel() {
    int v = (blockIdx.x * blockDim.x + threadIdx.x) >> 5;
    int lane = threadIdx.x & 31;
    if (v >= NN) return;
    int beg = g_rowptr[v], end = g_rowptr[v + 1];
    float snd0 = g_snd[v * 3 + 0], snd1 = g_snd[v * 3 + 1], snd2 = g_snd[v * 3 + 2];

    float m0 = -1e30f, m1 = -1e30f, m2 = -1e30f;
    for (int e = beg + lane; e < end; e += 32) {
        int s = g_csrsrc[e];
        m0 = fmaxf(m0, leaky(g_sns[s * 3 + 0] + snd0));
        m1 = fmaxf(m1, leaky(g_sns[s * 3 + 1] + snd1));
        m2 = fmaxf(m2, leaky(g_sns[s * 3 + 2] + snd2));
    }
#pragma unroll
    for (int o = 16; o; o >>= 1) {
        m0 = fmaxf(m0, __shfl_xor_sync(0xffffffffu, m0, o));
        m1 = fmaxf(m1, __shfl_xor_sync(0xffffffffu, m1, o));
        m2 = fmaxf(m2, __shfl_xor_sync(0xffffffffu, m2, o));
    }

    float acc[12];
#pragma unroll
    for (int j = 0; j < 12; j++) acc[j] = 0.f;
    float ws0 = 0.f, ws1 = 0.f, ws2 = 0.f;

    for (int e = beg; e < end; e++) {
        int s = g_csrsrc[e];
        float w0 = __expf(leaky(g_sns[s * 3 + 0] + snd0) - m0);
        float w1 = __expf(leaky(g_sns[s * 3 + 1] + snd1) - m1);
        float w2 = __expf(leaky(g_sns[s * 3 + 2] + snd2) - m2);
        ws0 += w0; ws1 += w1; ws2 += w2;
        const float* hr = g_h + (size_t)s * HD;
#pragma unroll
        for (int j = 0; j < 12; j++) {
            float wv = (j < 4) ? w0 : (j < 8) ? w1 : w2;
            acc[j] += wv * hr[j * 32 + lane];
        }
    }

    float r0 = ws0 > 0.f ? 1.f / ws0 : 0.f;
    float r1 = ws1 > 0.f ? 1.f / ws1 : 0.f;
    float r2 = ws2 > 0.f ? 1.f / ws2 : 0.f;
    __nv_bfloat16* ah = g_agghi + (size_t)v * HD;
    __nv_bfloat16* al = g_agglo + (size_t)v * HD;
#pragma unroll
    for (int j = 0; j < 12; j++) {
        float rv = (j < 4) ? r0 : (j < 8) ? r1 : r2;
        float val = acc[j] * rv;
        __nv_bfloat16 h, l; split_bf16(val, h, l);
        ah[j * 32 + lane] = h;
        al[j * 32 + lane] = l;
    }
}

// ---------------- gate ----------------
__global__ void gate_kernel(const float* __restrict__ p2w, const float* __restrict__ p2b) {
    int w = (blockIdx.x * blockDim.x + threadIdx.x) >> 5;
    int lane = threadIdx.x & 31;
    if (w >= NN) return;
    const float* hr = g_hidden + (size_t)w * TWO_D;
    float s = 0.f;
#pragma unroll
    for (int j = 0; j < 8; j++) {
        int f = j * 32 + lane;
        s += hr[f] * p2w[f];
    }
#pragma unroll
    for (int o = 16; o; o >>= 1) s += __shfl_xor_sync(0xffffffffu, s, o);
    if (lane == 0) g_gate[w] = s + p2b[0];
}

// ---------------- global attention pooling ----------------
__global__ void pool_kernel(const float* __restrict__ feat, float* __restrict__ out, float scale) {
    int g = blockIdx.x;
    int d = threadIdx.x;
    int s = g_gstart[g], e = g_gend[g];
    __shared__ float red[128];

    float m = -1e30f;
    for (int i = s + d; i < e; i += 128) m = fmaxf(m, g_gate[i]);
    red[d] = m; __syncthreads();
    for (int o = 64; o; o >>= 1) { if (d < o) red[d] = fmaxf(red[d], red[d + o]); __syncthreads(); }
    m = red[0]; __syncthreads();

    float sum = 0.f;
    for (int i = s + d; i < e; i += 128) sum += __expf(g_gate[i] - m);
    red[d] = sum; __syncthreads();
    for (int o = 64; o; o >>= 1) { if (d < o) red[d] += red[d + o]; __syncthreads(); }
    sum = red[0]; __syncthreads();

    float accv = 0.f;
    for (int i = s; i < e; i++) {
        float wv = __expf(g_gate[i] - m);
        accv += wv * feat[(size_t)i * DD + d];
    }
    if (e > s && sum > 0.f) out[g * DD + d] += scale * accv / sum;
}

// ---------------- launch ----------------
extern "C" void kernel_launch(void* const* d_in, const int* in_sizes, int n_in,
                              void* d_out, int out_size)
{
    const float* feat    = (const float*)d_in[0];
    const int*   src     = (const int*)d_in[1];
    const int*   dst     = (const int*)d_in[2];
    const int*   gid     = (const int*)d_in[3];
    const float* fc_w    = (const float*)d_in[4];
    const float* a_ns    = (const float*)d_in[5];
    const float* a_nd    = (const float*)d_in[6];
    const float* trans_w = (const float*)d_in[7];
    const float* trans_b = (const float*)d_in[8];
    const float* p1_w    = (const float*)d_in[9];
    const float* p1_b    = (const float*)d_in[10];
    const float* p2_w    = (const float*)d_in[11];
    const float* p2_b    = (const float*)d_in[12];
    float* out = (float*)d_out;

    float *p_h, *p_featA, *p_featB, *p_hidden;
    cudaGetSymbolAddress((void**)&p_h, g_h);
    cudaGetSymbolAddress((void**)&p_featA, g_featA);
    cudaGetSymbolAddress((void**)&p_featB, g_featB);
    cudaGetSymbolAddress((void**)&p_hidden, g_hidden);

    __nv_bfloat16 *p_fhiA, *p_floA, *p_fhiB, *p_floB, *p_agghi, *p_agglo;
    __nv_bfloat16 *p_wfchi, *p_wfclo, *p_wtrhi, *p_wtrlo, *p_wp1hi, *p_wp1lo;
    cudaGetSymbolAddress((void**)&p_fhiA, g_fhiA);
    cudaGetSymbolAddress((void**)&p_floA, g_floA);
    cudaGetSymbolAddress((void**)&p_fhiB, g_fhiB);
    cudaGetSymbolAddress((void**)&p_floB, g_floB);
    cudaGetSymbolAddress((void**)&p_agghi, g_agghi);
    cudaGetSymbolAddress((void**)&p_agglo, g_agglo);
    cudaGetSymbolAddress((void**)&p_wfchi, g_wfchi);
    cudaGetSymbolAddress((void**)&p_wfclo, g_wfclo);
    cudaGetSymbolAddress((void**)&p_wtrhi, g_wtrhi);
    cudaGetSymbolAddress((void**)&p_wtrlo, g_wtrlo);
    cudaGetSymbolAddress((void**)&p_wp1hi, g_wp1hi);
    cudaGetSymbolAddress((void**)&p_wp1lo, g_wp1lo);

    const int SMEM_GEMM = (2*2*SA_MAT + 2*2*SB_MAT) * (int)sizeof(__nv_bfloat16);
    cudaFuncSetAttribute(gemm_bf16split, cudaFuncAttributeMaxDynamicSharedMemorySize, SMEM_GEMM);

    // init output, input copy+split, weight splits
    zero_f_kernel<<<(GG * DD + 255) / 256, 256>>>(out, GG * DD);
    copy_split_kernel<<<(NN * DD + 255) / 256, 256>>>(feat);
    convert_split_kernel<<<(LL*HD*DD + 255) / 256, 256>>>(fc_w, p_wfchi, p_wfclo, LL*HD*DD);
    convert_split_kernel<<<(LL*DD*HD + 255) / 256, 256>>>(trans_w, p_wtrhi, p_wtrlo, LL*DD*HD);
    convert_split_kernel<<<(LL*TWO_D*DD + 255) / 256, 256>>>(p1_w, p_wp1hi, p_wp1lo, LL*TWO_D*DD);

    // CSR build (by dst)
    csr_init_kernel<<<(NN + 255) / 256, 256>>>();
    hist_kernel<<<(EE + 255) / 256, 256>>>(dst);
    scan_kernel<<<1, 1024>>>();
    scatter_kernel<<<(EE + 255) / 256, 256>>>(src, dst);

    // graph node ranges
    gb_init_kernel<<<1, GG>>>();
    gbounds_kernel<<<(NN + 255) / 256, 256>>>(gid);

    const int warpBlocks = (NN + 7) / 8;
    const int gx = (NN + 127) / 128;
    for (int d = 0; d < LL; d++) {
        int pp = d & 1;
        float* fin  = pp ? p_featB : p_featA;
        float* fout = pp ? p_featA : p_featB;
        __nv_bfloat16* finhi = pp ? p_fhiB : p_fhiA;
        __nv_bfloat16* finlo = pp ? p_floB : p_floA;
        __nv_bfloat16* fouthi = pp ? p_fhiA : p_fhiB;
        __nv_bfloat16* foutlo = pp ? p_floA : p_floB;

        // h = fin @ fc_w[d]^T   [N, 384]
        dim3 g1(gx, HD / 64);
        gemm_bf16split<<<g1, 256, SMEM_GEMM>>>(NN, HD, DD,
            finhi, finlo, p_wfchi + (size_t)d * HD * DD, p_wfclo + (size_t)d * HD * DD,
            nullptr, nullptr, p_h, nullptr, nullptr, 0);

        attn_score_kernel<<<warpBlocks, 256>>>(a_ns + (size_t)d * HD, a_nd + (size_t)d * HD);
        gat_edge_kernel<<<warpBlocks, 256>>>();

        // fout = relu?(agg @ trans_w[d]^T + b) + fin   [N, 128] (+ bf16 split out)
        dim3 g2(gx, DD / 64);
        gemm_bf16split<<<g2, 256, SMEM_GEMM>>>(NN, DD, HD,
            p_agghi, p_agglo, p_wtrhi + (size_t)d * DD * HD, p_wtrlo + (size_t)d * DD * HD,
            trans_b + (size_t)d * DD, fin, fout, fouthi, foutlo, (d < LL - 1) ? 1 : 0);

        // hidden = relu(fout @ p1_w[d]^T + b)   [N, 256]
        dim3 g3(gx, TWO_D / 64);
        gemm_bf16split<<<g3, 256, SMEM_GEMM>>>(NN, TWO_D, DD,
            fouthi, foutlo, p_wp1hi + (size_t)d * TWO_D * DD, p_wp1lo + (size_t)d * TWO_D * DD,
            p1_b + (size_t)d * TWO_D, nullptr, p_hidden, nullptr, nullptr, 1);

        gate_kernel<<<warpBlocks, 256>>>(p2_w + (size_t)d * TWO_D, p2_b + d);
        pool_kernel<<<GG, 128>>>(fout, out, 1.0f / LL);
    }
}

// round 6
// speedup vs baseline: 1.8640x; 1.0139x over previous
#include <cuda_runtime.h>
#include <cuda_bf16.h>
#include <stdint.h>
#include <math.h>

typedef unsigned int u32;

#define NN 20000
#define EE 320000
#define DD 128
#define HH 3
#define HD (HH*DD)      /* 384 */
#define LL 3
#define GG 64
#define TWO_D (2*DD)    /* 256 */
#define NEG_SLOPE 0.2f

// ---------------- scratch (device globals; no allocation allowed) ----------------
__device__ float g_h[(size_t)NN*HD];
__device__ float g_featA[(size_t)NN*DD];
__device__ float g_featB[(size_t)NN*DD];
__device__ float g_gate[NN];
__device__ float g_sns[NN*HH];
__device__ float g_snd[NN*HH];
__device__ int   g_deg[NN];
__device__ int   g_rowptr[NN+1];
__device__ int   g_cursor[NN];
__device__ int   g_csrsrc[EE];
__device__ int   g_gstart[GG];
__device__ int   g_gend[GG];

// bf16 split buffers
__device__ __nv_bfloat16 g_fhiA[(size_t)NN*DD];
__device__ __nv_bfloat16 g_floA[(size_t)NN*DD];
__device__ __nv_bfloat16 g_fhiB[(size_t)NN*DD];
__device__ __nv_bfloat16 g_floB[(size_t)NN*DD];
__device__ __nv_bfloat16 g_agghi[(size_t)NN*HD];
__device__ __nv_bfloat16 g_agglo[(size_t)NN*HD];
__device__ __nv_bfloat16 g_wfchi[(size_t)LL*HD*DD];
__device__ __nv_bfloat16 g_wfclo[(size_t)LL*HD*DD];
__device__ __nv_bfloat16 g_wtrhi[(size_t)LL*DD*HD];
__device__ __nv_bfloat16 g_wtrlo[(size_t)LL*DD*HD];
__device__ __nv_bfloat16 g_wp1hi[(size_t)LL*TWO_D*DD];
__device__ __nv_bfloat16 g_wp1lo[(size_t)LL*TWO_D*DD];

__device__ __forceinline__ void split_bf16(float v, __nv_bfloat16& hi, __nv_bfloat16& lo) {
    hi = __float2bfloat16_rn(v);
    lo = __float2bfloat16_rn(v - __bfloat162float(hi));
}

// ---------------- small utility kernels ----------------
__global__ void zero_f_kernel(float* p, int n) {
    int i = blockIdx.x*blockDim.x + threadIdx.x;
    if (i < n) p[i] = 0.f;
}

__global__ void copy_split_kernel(const float* __restrict__ srcp) {
    int i = blockIdx.x*blockDim.x + threadIdx.x;
    if (i < NN*DD) {
        float v = srcp[i];
        g_featA[i] = v;
        __nv_bfloat16 hi, lo; split_bf16(v, hi, lo);
        g_fhiA[i] = hi; g_floA[i] = lo;
    }
}

__global__ void convert_split_kernel(const float* __restrict__ srcp,
                                     __nv_bfloat16* __restrict__ hi,
                                     __nv_bfloat16* __restrict__ lo, int n) {
    int i = blockIdx.x*blockDim.x + threadIdx.x;
    if (i < n) {
        __nv_bfloat16 h, l; split_bf16(srcp[i], h, l);
        hi[i] = h; lo[i] = l;
    }
}

__global__ void csr_init_kernel() {
    int i = blockIdx.x*blockDim.x + threadIdx.x;
    if (i < NN) g_deg[i] = 0;
}

__global__ void hist_kernel(const int* __restrict__ dst) {
    int e = blockIdx.x*blockDim.x + threadIdx.x;
    if (e < EE) atomicAdd(&g_deg[dst[e]], 1);
}

__global__ void scan_kernel() {
    __shared__ int part[1024];
    int t = threadIdx.x;
    const int CH = 20;
    int base = t * CH;
    int local[CH];
    int s = 0;
#pragma unroll
    for (int i = 0; i < CH; i++) {
        int idx = base + i;
        int v = (idx < NN) ? g_deg[idx] : 0;
        local[i] = s;
        s += v;
    }
    part[t] = s;
    __syncthreads();
    for (int off = 1; off < 1024; off <<= 1) {
        int v = (t >= off) ? part[t - off] : 0;
        __syncthreads();
        part[t] += v;
        __syncthreads();
    }
    int offset = (t > 0) ? part[t - 1] : 0;
#pragma unroll
    for (int i = 0; i < CH; i++) {
        int idx = base + i;
        if (idx < NN) {
            int r = offset + local[i];
            g_rowptr[idx] = r;
            g_cursor[idx] = r;
        }
    }
    if (t == 0) g_rowptr[NN] = part[1023];
}

__global__ void scatter_kernel(const int* __restrict__ src, const int* __restrict__ dst) {
    int e = blockIdx.x*blockDim.x + threadIdx.x;
    if (e < EE) {
        int p = atomicAdd(&g_cursor[dst[e]], 1);
        g_csrsrc[p] = src[e];
    }
}

__global__ void gb_init_kernel() {
    int g = threadIdx.x;
    if (g < GG) { g_gstart[g] = NN; g_gend[g] = 0; }
}

__global__ void gbounds_kernel(const int* __restrict__ gid) {
    int i = blockIdx.x*blockDim.x + threadIdx.x;
    if (i < NN) {
        int g = gid[i];
        atomicMin(&g_gstart[g], i);
        atomicMax(&g_gend[g], i + 1);
    }
}

// ---------------- tensor-core GEMM: C[M,Nd] = A[M,K] @ B[Nd,K]^T ----------------
// bf16 split-precision: C = Ahi*Bhi + Ahi*Blo + Alo*Bhi (fp32 accumulate)
// Block tile 128(M) x 64(N), K-chunk 32, 256 threads (8 warps 4x2),
// warp tile 32x32 via mma.sync.m16n8k16 + ldmatrix, double-buffered smem.
// Optional fused gate epilogue: gate[m] += sum_n relu(v[m,n]) * p2w[n] (atomicAdd)

__device__ __forceinline__ void ldm_x4(u32 addr, u32& r0, u32& r1, u32& r2, u32& r3) {
    asm volatile("ldmatrix.sync.aligned.m8n8.x4.shared.b16 {%0,%1,%2,%3}, [%4];"
        : "=r"(r0), "=r"(r1), "=r"(r2), "=r"(r3) : "r"(addr));
}

__device__ __forceinline__ void mma16816(float* c, const u32* a, const u32* b) {
    asm volatile(
        "mma.sync.aligned.m16n8k16.row.col.f32.bf16.bf16.f32 "
        "{%0,%1,%2,%3}, {%4,%5,%6,%7}, {%8,%9}, {%0,%1,%2,%3};"
        : "+f"(c[0]), "+f"(c[1]), "+f"(c[2]), "+f"(c[3])
        : "r"(a[0]), "r"(a[1]), "r"(a[2]), "r"(a[3]), "r"(b[0]), "r"(b[1]));
}

__device__ __forceinline__ uint4 ldz(const __nv_bfloat16* p, int row, int K, int kb, int M) {
    if (row < M) return *(const uint4*)(p + (size_t)row * K + kb);
    uint4 z; z.x = 0u; z.y = 0u; z.z = 0u; z.w = 0u;
    return z;
}

#define A_PAD 40   /* row stride in bf16 elems: 80B -> 20-bank shift, conflict-free */
#define SA_MAT (128*A_PAD)
#define SB_MAT (64*A_PAD)

#define GFETCH(kc) { \
    int kb = ((kc) << 5) + aq; \
    pa00 = ldz(Ahi, m0 + ar0,      K, kb, M); \
    pa01 = ldz(Ahi, m0 + ar0 + 64, K, kb, M); \
    pa10 = ldz(Alo, m0 + ar0,      K, kb, M); \
    pa11 = ldz(Alo, m0 + ar0 + 64, K, kb, M); \
    pb0  = *(const uint4*)(Bhi + (size_t)(n0 + br0) * K + kb); \
    pb1  = *(const uint4*)(Blo + (size_t)(n0 + br0) * K + kb); \
}

#define GSTORE(st) { \
    *(uint4*)(sA + ((st)*2+0)*SA_MAT + ar0*A_PAD + aq)        = pa00; \
    *(uint4*)(sA + ((st)*2+0)*SA_MAT + (ar0+64)*A_PAD + aq)   = pa01; \
    *(uint4*)(sA + ((st)*2+1)*SA_MAT + ar0*A_PAD + aq)        = pa10; \
    *(uint4*)(sA + ((st)*2+1)*SA_MAT + (ar0+64)*A_PAD + aq)   = pa11; \
    *(uint4*)(sB + ((st)*2+0)*SB_MAT + br0*A_PAD + aq)        = pb0; \
    *(uint4*)(sB + ((st)*2+1)*SB_MAT + br0*A_PAD + aq)        = pb1; \
}

__global__ void __launch_bounds__(256, 2) gemm_bf16split(
    int M, int Nd, int K,
    const __nv_bfloat16* __restrict__ Ahi, const __nv_bfloat16* __restrict__ Alo,
    const __nv_bfloat16* __restrict__ Bhi, const __nv_bfloat16* __restrict__ Blo,
    const float* __restrict__ bias, const float* __restrict__ resid,
    float* __restrict__ C, __nv_bfloat16* __restrict__ Chi, __nv_bfloat16* __restrict__ Clo,
    int do_relu, float* __restrict__ gatep, const float* __restrict__ p2w)
{
    extern __shared__ __nv_bfloat16 smem[];
    __nv_bfloat16* sA = smem;                // [2 stages][2 hl][128*A_PAD]
    __nv_bfloat16* sB = smem + 2*2*SA_MAT;   // [2 stages][2 hl][64*A_PAD]

    const int tid  = threadIdx.x;
    const int lane = tid & 31;
    const int w    = tid >> 5;
    const int wm   = w & 3;     // 4 warps along M (32 rows each)
    const int wn   = w >> 2;    // 2 warps along N (32 cols each)
    const int m0   = blockIdx.x * 128;
    const int n0   = blockIdx.y * 64;
    const int nk   = K >> 5;

    float acc[2][4][4];
#pragma unroll
    for (int a = 0; a < 2; a++)
#pragma unroll
        for (int b = 0; b < 4; b++)
#pragma unroll
            for (int c = 0; c < 4; c++) acc[a][b][c] = 0.f;

    const u32 sA_u = (u32)__cvta_generic_to_shared(sA);
    const u32 sB_u = (u32)__cvta_generic_to_shared(sB);

    // ldmatrix lane addressing
    const int a_row_in = (lane & 7) + ((lane >> 3) & 1) * 8;
    const int a_kofs   = (lane >> 4) * 8;
    const int b_sub    = lane >> 3;
    const int b_row_in = (lane & 7) + (b_sub >> 1) * 8;
    const int b_kofs   = (b_sub & 1) * 8;

    // per-thread global load mapping (32 k-elems per row chunk, 4 threads/row)
    const int ar0 = tid >> 2;
    const int aq  = (tid & 3) * 8;
    const int br0 = tid >> 2;

    uint4 pa00, pa01, pa10, pa11, pb0, pb1;

    GFETCH(0);
    GSTORE(0);
    __syncthreads();

    for (int kc = 0; kc < nk; kc++) {
        const int cur = kc & 1;
        if (kc + 1 < nk) GFETCH(kc + 1);

#pragma unroll
        for (int ks = 0; ks < 2; ks++) {
            u32 Af[2][2][4];
            u32 Bf[2][4][2];
#pragma unroll
            for (int hl = 0; hl < 2; hl++) {
                const u32 abase = sA_u +
                    (u32)(((cur * 2 + hl) * 128 + wm * 32) * A_PAD) * 2u;
#pragma unroll
                for (int mt = 0; mt < 2; mt++) {
                    u32 addr = abase +
                        (u32)((mt * 16 + a_row_in) * A_PAD + ks * 16 + a_kofs) * 2u;
                    ldm_x4(addr, Af[hl][mt][0], Af[hl][mt][1], Af[hl][mt][2], Af[hl][mt][3]);
                }
                const u32 bbase = sB_u +
                    (u32)(((cur * 2 + hl) * 64 + wn * 32) * A_PAD) * 2u;
#pragma unroll
                for (int pr = 0; pr < 2; pr++) {
                    u32 addr2 = bbase +
                        (u32)((pr * 16 + b_row_in) * A_PAD + ks * 16 + b_kofs) * 2u;
                    u32 q0, q1, q2, q3;
                    ldm_x4(addr2, q0, q1, q2, q3);
                    Bf[hl][pr * 2 + 0][0] = q0; Bf[hl][pr * 2 + 0][1] = q1;
                    Bf[hl][pr * 2 + 1][0] = q2; Bf[hl][pr * 2 + 1][1] = q3;
                }
            }
#pragma unroll
            for (int mt = 0; mt < 2; mt++)
#pragma unroll
                for (int nt = 0; nt < 4; nt++) {
                    mma16816(acc[mt][nt], Af[0][mt], Bf[0][nt]);  // hi*hi
                    mma16816(acc[mt][nt], Af[0][mt], Bf[1][nt]);  // hi*lo
                    mma16816(acc[mt][nt], Af[1][mt], Bf[0][nt]);  // lo*hi
                }
        }

        if (kc + 1 < nk) GSTORE((kc + 1) & 1);
        __syncthreads();
    }

    // epilogue
    const int gr = lane >> 2;
    const int gc = (lane & 3) * 2;
#pragma unroll
    for (int mt = 0; mt < 2; mt++) {
#pragma unroll
        for (int half = 0; half < 2; half++) {
            int m = m0 + wm * 32 + mt * 16 + gr + half * 8;
            if (m >= M) continue;
            float gpart = 0.f;
#pragma unroll
            for (int nt = 0; nt < 4; nt++) {
                int n = n0 + wn * 32 + nt * 8 + gc;
                float v0 = acc[mt][nt][half * 2 + 0];
                float v1 = acc[mt][nt][half * 2 + 1];
                if (bias) { v0 += bias[n]; v1 += bias[n + 1]; }
                if (do_relu) { v0 = fmaxf(v0, 0.f); v1 = fmaxf(v1, 0.f); }
                if (resid) {
                    v0 += resid[(size_t)m * Nd + n];
                    v1 += resid[(size_t)m * Nd + n + 1];
                }
                if (gatep) {
                    gpart += v0 * __ldg(p2w + n) + v1 * __ldg(p2w + n + 1);
                }
                if (C) {
                    float2 vv; vv.x = v0; vv.y = v1;
                    *(float2*)(C + (size_t)m * Nd + n) = vv;
                }
                if (Chi) {
                    __nv_bfloat16 h0, l0, h1, l1;
                    split_bf16(v0, h0, l0);
                    split_bf16(v1, h1, l1);
                    __nv_bfloat162 hh; hh.x = h0; hh.y = h1;
                    __nv_bfloat162 ll; ll.x = l0; ll.y = l1;
                    *(__nv_bfloat162*)(Chi + (size_t)m * Nd + n) = hh;
                    *(__nv_bfloat162*)(Clo + (size_t)m * Nd + n) = ll;
                }
            }
            if (gatep) atomicAdd(gatep + m, gpart);
        }
    }
}

// ---------------- per-node attention scores ----------------
__global__ void attn_score_kernel(const float* __restrict__ ans, const float* __restrict__ andv) {
    int w = (blockIdx.x * blockDim.x + threadIdx.x) >> 5;
    int lane = threadIdx.x & 31;
    if (w >= NN) return;
    float s0 = 0.f, s1 = 0.f, s2 = 0.f, t0 = 0.f, t1 = 0.f, t2 = 0.f;
    const float* hr = g_h + (size_t)w * HD;
#pragma unroll
    for (int j = 0; j < 12; j++) {
        int f = j * 32 + lane;
        float hv = hr[f];
        float av = ans[f];
        float bv = andv[f];
        if (j < 4)      { s0 += hv * av; t0 += hv * bv; }
        else if (j < 8) { s1 += hv * av; t1 += hv * bv; }
        else            { s2 += hv * av; t2 += hv * bv; }
    }
#pragma unroll
    for (int o = 16; o; o >>= 1) {
        s0 += __shfl_xor_sync(0xffffffffu, s0, o);
        s1 += __shfl_xor_sync(0xffffffffu, s1, o);
        s2 += __shfl_xor_sync(0xffffffffu, s2, o);
        t0 += __shfl_xor_sync(0xffffffffu, t0, o);
        t1 += __shfl_xor_sync(0xffffffffu, t1, o);
        t2 += __shfl_xor_sync(0xffffffffu, t2, o);
    }
    if (lane == 0) {
        g_sns[w * 3 + 0] = s0; g_sns[w * 3 + 1] = s1; g_sns[w * 3 + 2] = s2;
        g_snd[w * 3 + 0] = t0; g_snd[w * 3 + 1] = t1; g_snd[w * 3 + 2] = t2;
    }
}

// ---------------- edge softmax + aggregation: one warp per dst node ----------------
__device__ __forceinline__ float leaky(float x) { return x > 0.f ? x : NEG_SLOPE * x; }

__global__ void gat_edge_kernel() {
    int v = (blockIdx.x * blockDim.x + threadIdx.x) >> 5;
    int lane = threadIdx.x & 31;
    if (v >= NN) return;
    int beg = g_rowptr[v], end = g_rowptr[v + 1];
    float snd0 = g_snd[v * 3 + 0], snd1 = g_snd[v * 3 + 1], snd2 = g_snd[v * 3 + 2];

    float m0 = -1e30f, m1 = -1e30f, m2 = -1e30f;
    for (int e = beg + lane; e < end; e += 32) {
        int s = g_csrsrc[e];
        m0 = fmaxf(m0, leaky(g_sns[s * 3 + 0] + snd0));
        m1 = fmaxf(m1, leaky(g_sns[s * 3 + 1] + snd1));
        m2 = fmaxf(m2, leaky(g_sns[s * 3 + 2] + snd2));
    }
#pragma unroll
    for (int o = 16; o; o >>= 1) {
        m0 = fmaxf(m0, __shfl_xor_sync(0xffffffffu, m0, o));
        m1 = fmaxf(m1, __shfl_xor_sync(0xffffffffu, m1, o));
        m2 = fmaxf(m2, __shfl_xor_sync(0xffffffffu, m2, o));
    }

    float acc[12];
#pragma unroll
    for (int j = 0; j < 12; j++) acc[j] = 0.f;
    float ws0 = 0.f, ws1 = 0.f, ws2 = 0.f;

    for (int e = beg; e < end; e++) {
        int s = g_csrsrc[e];
        float w0 = __expf(leaky(g_sns[s * 3 + 0] + snd0) - m0);
        float w1 = __expf(leaky(g_sns[s * 3 + 1] + snd1) - m1);
        float w2 = __expf(leaky(g_sns[s * 3 + 2] + snd2) - m2);
        ws0 += w0; ws1 += w1; ws2 += w2;
        const float* hr = g_h + (size_t)s * HD;
#pragma unroll
        for (int j = 0; j < 12; j++) {
            float wv = (j < 4) ? w0 : (j < 8) ? w1 : w2;
            acc[j] += wv * hr[j * 32 + lane];
        }
    }

    float r0 = ws0 > 0.f ? 1.f / ws0 : 0.f;
    float r1 = ws1 > 0.f ? 1.f / ws1 : 0.f;
    float r2 = ws2 > 0.f ? 1.f / ws2 : 0.f;
    __nv_bfloat16* ah = g_agghi + (size_t)v * HD;
    __nv_bfloat16* al = g_agglo + (size_t)v * HD;
#pragma unroll
    for (int j = 0; j < 12; j++) {
        float rv = (j < 4) ? r0 : (j < 8) ? r1 : r2;
        float val = acc[j] * rv;
        __nv_bfloat16 h, l; split_bf16(val, h, l);
        ah[j * 32 + lane] = h;
        al[j * 32 + lane] = l;
    }
}

// ---------------- global attention pooling ----------------
__global__ void pool_kernel(const float* __restrict__ feat, float* __restrict__ out, float scale) {
    int g = blockIdx.x;
    int d = threadIdx.x;
    int s = g_gstart[g], e = g_gend[g];
    __shared__ float red[128];

    float m = -1e30f;
    for (int i = s + d; i < e; i += 128) m = fmaxf(m, g_gate[i]);
    red[d] = m; __syncthreads();
    for (int o = 64; o; o >>= 1) { if (d < o) red[d] = fmaxf(red[d], red[d + o]); __syncthreads(); }
    m = red[0]; __syncthreads();

    float sum = 0.f;
    for (int i = s + d; i < e; i += 128) sum += __expf(g_gate[i] - m);
    red[d] = sum; __syncthreads();
    for (int o = 64; o; o >>= 1) { if (d < o) red[d] += red[d + o]; __syncthreads(); }
    sum = red[0]; __syncthreads();

    float accv = 0.f;
    for (int i = s; i < e; i++) {
        float wv = __expf(g_gate[i] - m);
        accv += wv * feat[(size_t)i * DD + d];
    }
    if (e > s && sum > 0.f) out[g * DD + d] += scale * accv / sum;
}

// ---------------- launch ----------------
extern "C" void kernel_launch(void* const* d_in, const int* in_sizes, int n_in,
                              void* d_out, int out_size)
{
    const float* feat    = (const float*)d_in[0];
    const int*   src     = (const int*)d_in[1];
    const int*   dst     = (const int*)d_in[2];
    const int*   gid     = (const int*)d_in[3];
    const float* fc_w    = (const float*)d_in[4];
    const float* a_ns    = (const float*)d_in[5];
    const float* a_nd    = (const float*)d_in[6];
    const float* trans_w = (const float*)d_in[7];
    const float* trans_b = (const float*)d_in[8];
    const float* p1_w    = (const float*)d_in[9];
    const float* p1_b    = (const float*)d_in[10];
    const float* p2_w    = (const float*)d_in[11];
    const float* p2_b    = (const float*)d_in[12];
    (void)p2_b;  // softmax over gate is invariant to the constant bias
    float* out = (float*)d_out;

    float *p_h, *p_featA, *p_featB, *p_gate;
    cudaGetSymbolAddress((void**)&p_h, g_h);
    cudaGetSymbolAddress((void**)&p_featA, g_featA);
    cudaGetSymbolAddress((void**)&p_featB, g_featB);
    cudaGetSymbolAddress((void**)&p_gate, g_gate);

    __nv_bfloat16 *p_fhiA, *p_floA, *p_fhiB, *p_floB, *p_agghi, *p_agglo;
    __nv_bfloat16 *p_wfchi, *p_wfclo, *p_wtrhi, *p_wtrlo, *p_wp1hi, *p_wp1lo;
    cudaGetSymbolAddress((void**)&p_fhiA, g_fhiA);
    cudaGetSymbolAddress((void**)&p_floA, g_floA);
    cudaGetSymbolAddress((void**)&p_fhiB, g_fhiB);
    cudaGetSymbolAddress((void**)&p_floB, g_floB);
    cudaGetSymbolAddress((void**)&p_agghi, g_agghi);
    cudaGetSymbolAddress((void**)&p_agglo, g_agglo);
    cudaGetSymbolAddress((void**)&p_wfchi, g_wfchi);
    cudaGetSymbolAddress((void**)&p_wfclo, g_wfclo);
    cudaGetSymbolAddress((void**)&p_wtrhi, g_wtrhi);
    cudaGetSymbolAddress((void**)&p_wtrlo, g_wtrlo);
    cudaGetSymbolAddress((void**)&p_wp1hi, g_wp1hi);
    cudaGetSymbolAddress((void**)&p_wp1lo, g_wp1lo);

    const int SMEM_GEMM = (2*2*SA_MAT + 2*2*SB_MAT) * (int)sizeof(__nv_bfloat16);
    cudaFuncSetAttribute(gemm_bf16split, cudaFuncAttributeMaxDynamicSharedMemorySize, SMEM_GEMM);

    const int gx = (NN + 127) / 128;
    const int warpBlocks = (NN + 7) / 8;

    // setup: launches 0..4
    zero_f_kernel<<<(GG * DD + 255) / 256, 256>>>(out, GG * DD);
    copy_split_kernel<<<(NN * DD + 255) / 256, 256>>>(feat);
    convert_split_kernel<<<(LL*HD*DD + 255) / 256, 256>>>(fc_w, p_wfchi, p_wfclo, LL*HD*DD);
    convert_split_kernel<<<(LL*DD*HD + 255) / 256, 256>>>(trans_w, p_wtrhi, p_wtrlo, LL*DD*HD);
    convert_split_kernel<<<(LL*TWO_D*DD + 255) / 256, 256>>>(p1_w, p_wp1hi, p_wp1lo, LL*TWO_D*DD);

    // launch #5: layer-0 h-GEMM (profiled by ncu -s 5 -c 1)
    gemm_bf16split<<<dim3(gx, HD / 64), 256, SMEM_GEMM>>>(NN, HD, DD,
        p_fhiA, p_floA, p_wfchi, p_wfclo,
        (const float*)0, (const float*)0, p_h,
        (__nv_bfloat16*)0, (__nv_bfloat16*)0, 0, (float*)0, (const float*)0);

    // CSR build (by dst)
    csr_init_kernel<<<(NN + 255) / 256, 256>>>();
    hist_kernel<<<(EE + 255) / 256, 256>>>(dst);
    scan_kernel<<<1, 1024>>>();
    scatter_kernel<<<(EE + 255) / 256, 256>>>(src, dst);

    // graph node ranges
    gb_init_kernel<<<1, GG>>>();
    gbounds_kernel<<<(NN + 255) / 256, 256>>>(gid);

    for (int d = 0; d < LL; d++) {
        int pp = d & 1;
        float* fin  = pp ? p_featB : p_featA;
        float* fout = pp ? p_featA : p_featB;
        __nv_bfloat16* finhi = pp ? p_fhiB : p_fhiA;
        __nv_bfloat16* finlo = pp ? p_floB : p_floA;
        __nv_bfloat16* fouthi = pp ? p_fhiA : p_fhiB;
        __nv_bfloat16* foutlo = pp ? p_floA : p_floB;

        if (d > 0) {
            // h = fin @ fc_w[d]^T   [N, 384]
            gemm_bf16split<<<dim3(gx, HD / 64), 256, SMEM_GEMM>>>(NN, HD, DD,
                finhi, finlo, p_wfchi + (size_t)d * HD * DD, p_wfclo + (size_t)d * HD * DD,
                (const float*)0, (const float*)0, p_h,
                (__nv_bfloat16*)0, (__nv_bfloat16*)0, 0, (float*)0, (const float*)0);
        }

        attn_score_kernel<<<warpBlocks, 256>>>(a_ns + (size_t)d * HD, a_nd + (size_t)d * HD);
        gat_edge_kernel<<<warpBlocks, 256>>>();

        // fout = relu?(agg @ trans_w[d]^T + b) + fin   [N, 128] (+ bf16 split out)
        gemm_bf16split<<<dim3(gx, DD / 64), 256, SMEM_GEMM>>>(NN, DD, HD,
            p_agghi, p_agglo, p_wtrhi + (size_t)d * DD * HD, p_wtrlo + (size_t)d * DD * HD,
            trans_b + (size_t)d * DD, fin, fout, fouthi, foutlo, (d < LL - 1) ? 1 : 0,
            (float*)0, (const float*)0);

        // gate[m] = sum_n relu(fout @ p1_w[d]^T + p1_b)[m,n] * p2_w[n]
        // (p2_b dropped: per-graph softmax is shift-invariant)
        zero_f_kernel<<<(NN + 255) / 256, 256>>>(p_gate, NN);
        gemm_bf16split<<<dim3(gx, TWO_D / 64), 256, SMEM_GEMM>>>(NN, TWO_D, DD,
            fouthi, foutlo, p_wp1hi + (size_t)d * TWO_D * DD, p_wp1lo + (size_t)d * TWO_D * DD,
            p1_b + (size_t)d * TWO_D, (const float*)0, (float*)0,
            (__nv_bfloat16*)0, (__nv_bfloat16*)0, 1,
            p_gate, p2_w + (size_t)d * TWO_D);

        pool_kernel<<<GG, 128>>>(fout, out, 1.0f / LL);
    }
}